// round 6
// baseline (speedup 1.0000x reference)
#include <cuda_runtime.h>
#include <cstdint>

#define NN 100000
#define EE 1600000
#define HH 128
#define H3 384
#define LL 3

// ---------------- scratch (static device globals; no allocation) ----------------
__device__ __align__(256) float g_m[(size_t)NN * HH];     // m = x @ W[l]
__device__ __align__(256) float g_agg[(size_t)NN * HH];   // scatter-add target
__device__ __align__(256) float g_gi[(size_t)NN * H3];    // agg @ w_ih^T + b_ih
__device__ __align__(256) float g_gh[(size_t)NN * H3];    // x   @ w_hh^T + b_hh
__device__ __align__(256) float g_x[(size_t)NN * HH];     // hidden state ping buffer
__device__ __align__(256) float g_wt_ih[(size_t)HH * H3]; // w_ih transposed -> [128][384]
__device__ __align__(256) float g_wt_hh[(size_t)HH * H3]; // w_hh transposed -> [128][384]
__device__ int g_idx64;                                    // 1 if edge_index buffer is int64

// ---------------- detect edge_index dtype ----------------
// int64 positive values < 2^31 have zero high words at odd 32-bit positions.
// int32 data has real indices there (all-zero over 2048 samples ~ impossible).
__global__ void detect_idx_kernel(const int* __restrict__ ei32) {
    int bad = 0;
    for (int i = threadIdx.x; i < 4096; i += blockDim.x) {
        if ((i & 1) && ei32[i] != 0) bad = 1;
    }
    bad = __syncthreads_or(bad);
    if (threadIdx.x == 0) g_idx64 = bad ? 0 : 1;
}

// ---------------- transpose [384][128] -> [128][384] ----------------
__global__ void transpose_w_kernel(const float* __restrict__ w, float* __restrict__ wt) {
    int i = blockIdx.x * blockDim.x + threadIdx.x;
    if (i < H3 * HH) {
        int j = i / HH;   // 0..383
        int k = i % HH;   // 0..127
        wt[k * H3 + j] = w[i];
    }
}

// ---------------- zero buffer (float4) ----------------
__global__ void zero_kernel(float4* __restrict__ p, int n4) {
    int i = blockIdx.x * blockDim.x + threadIdx.x;
    if (i < n4) p[i] = make_float4(0.f, 0.f, 0.f, 0.f);
}

// ---------------- tiled fp32 GEMM: C[nrows x 128k] = A[nrows x 128] @ B[128 x ncols] (+bias) ----
#define BM 64
#define KC 32
__global__ __launch_bounds__(256) void gemm_bias_kernel(
    const float* __restrict__ A, const float* __restrict__ B,
    const float* __restrict__ bias, float* __restrict__ C,
    int nrows, int ncols)
{
    __shared__ __align__(16) float Ast[KC][BM + 4];
    __shared__ __align__(16) float Bs[KC][128];

    const int tid = threadIdx.x;          // 256 threads
    const int tx  = tid & 15;             // cols tx*8 .. tx*8+7
    const int ty  = tid >> 4;             // rows ty*4 .. ty*4+3
    const int row0 = blockIdx.x * BM;
    const int col0 = blockIdx.y * 128;

    float acc[4][8];
#pragma unroll
    for (int i = 0; i < 4; i++)
#pragma unroll
        for (int j = 0; j < 8; j++) acc[i][j] = 0.f;

    const int ka = tid & 31;
    const int ra = tid >> 5;

    for (int kc = 0; kc < HH; kc += KC) {
#pragma unroll
        for (int i = 0; i < 8; i++) {
            int r = ra + i * 8;
            int grow = row0 + r;
            float v = (grow < nrows) ? A[(size_t)grow * HH + kc + ka] : 0.f;
            Ast[ka][r] = v;
        }
#pragma unroll
        for (int idx = tid; idx < KC * 128; idx += 256) {
            int kb = idx >> 7;
            int cb = idx & 127;
            Bs[kb][cb] = B[(size_t)(kc + kb) * ncols + col0 + cb];
        }
        __syncthreads();

#pragma unroll 8
        for (int k = 0; k < KC; k++) {
            float4 a  = *(const float4*)&Ast[k][ty * 4];
            float4 b0 = *(const float4*)&Bs[k][tx * 8];
            float4 b1 = *(const float4*)&Bs[k][tx * 8 + 4];
            float av[4] = {a.x, a.y, a.z, a.w};
            float bv[8] = {b0.x, b0.y, b0.z, b0.w, b1.x, b1.y, b1.z, b1.w};
#pragma unroll
            for (int i = 0; i < 4; i++)
#pragma unroll
                for (int j = 0; j < 8; j++) acc[i][j] += av[i] * bv[j];
        }
        __syncthreads();
    }

    float bvals[8];
#pragma unroll
    for (int j = 0; j < 8; j++) bvals[j] = bias ? bias[col0 + tx * 8 + j] : 0.f;

#pragma unroll
    for (int i = 0; i < 4; i++) {
        int grow = row0 + ty * 4 + i;
        if (grow < nrows) {
            float4 o0 = make_float4(acc[i][0] + bvals[0], acc[i][1] + bvals[1],
                                    acc[i][2] + bvals[2], acc[i][3] + bvals[3]);
            float4 o1 = make_float4(acc[i][4] + bvals[4], acc[i][5] + bvals[5],
                                    acc[i][6] + bvals[6], acc[i][7] + bvals[7]);
            float* crow = &C[(size_t)grow * ncols + col0 + tx * 8];
            *(float4*)(crow)     = o0;
            *(float4*)(crow + 4) = o1;
        }
    }
}

// ---------------- edge gather * weight -> vector red scatter-add ----------------
// one warp per edge; each lane handles one float4 (32 lanes * 4 = 128 features)
__global__ __launch_bounds__(256) void edge_scatter_kernel(
    const float* __restrict__ m, const float* __restrict__ ew,
    const void* __restrict__ ei, float* __restrict__ agg)
{
    long long gid = (long long)blockIdx.x * blockDim.x + threadIdx.x;
    int edge = (int)(gid >> 5);
    int lane = (int)(gid & 31);
    if (edge >= EE) return;

    int s, d;
    if (g_idx64) {
        const long long* e64 = (const long long*)ei;
        s = (int)e64[edge];
        d = (int)e64[EE + edge];
    } else {
        const int* e32 = (const int*)ei;
        s = e32[edge];
        d = e32[EE + edge];
    }
    // safety clamp: a bad index becomes a wrong answer (diagnosable), not an IMA
    if ((unsigned)s >= NN || (unsigned)d >= NN) return;

    float w = ew[edge];
    float4 v = *(const float4*)(m + (size_t)s * HH + lane * 4);
    v.x *= w; v.y *= w; v.z *= w; v.w *= w;

    float* dstp = agg + (size_t)d * HH + lane * 4;
    asm volatile("red.global.add.v4.f32 [%0], {%1, %2, %3, %4};"
                 :: "l"(dstp), "f"(v.x), "f"(v.y), "f"(v.z), "f"(v.w)
                 : "memory");
}

// ---------------- GRU elementwise ----------------
__global__ __launch_bounds__(256) void gru_elem_kernel(
    const float* __restrict__ gi, const float* __restrict__ gh,
    const float* __restrict__ x, float* __restrict__ xout, int n4)
{
    int idx = blockIdx.x * blockDim.x + threadIdx.x;
    if (idx >= n4) return;
    int node = idx >> 5;       // 32 float4 per node (H=128)
    int c4   = idx & 31;

    const float4* gi4 = (const float4*)gi;  // node stride 96 float4
    const float4* gh4 = (const float4*)gh;
    size_t base = (size_t)node * 96 + c4;

    float4 ir = gi4[base];
    float4 iz = gi4[base + 32];
    float4 in_ = gi4[base + 64];
    float4 hr = gh4[base];
    float4 hz = gh4[base + 32];
    float4 hn = gh4[base + 64];
    float4 xv = ((const float4*)x)[idx];

    float4 o;
    {
        float r  = 1.f / (1.f + __expf(-(ir.x + hr.x)));
        float zg = 1.f / (1.f + __expf(-(iz.x + hz.x)));
        float nn = tanhf(in_.x + r * hn.x);
        o.x = (1.f - zg) * nn + zg * xv.x;
    }
    {
        float r  = 1.f / (1.f + __expf(-(ir.y + hr.y)));
        float zg = 1.f / (1.f + __expf(-(iz.y + hz.y)));
        float nn = tanhf(in_.y + r * hn.y);
        o.y = (1.f - zg) * nn + zg * xv.y;
    }
    {
        float r  = 1.f / (1.f + __expf(-(ir.z + hr.z)));
        float zg = 1.f / (1.f + __expf(-(iz.z + hz.z)));
        float nn = tanhf(in_.z + r * hn.z);
        o.z = (1.f - zg) * nn + zg * xv.z;
    }
    {
        float r  = 1.f / (1.f + __expf(-(ir.w + hr.w)));
        float zg = 1.f / (1.f + __expf(-(iz.w + hz.w)));
        float nn = tanhf(in_.w + r * hn.w);
        o.w = (1.f - zg) * nn + zg * xv.w;
    }
    ((float4*)xout)[idx] = o;
}

// ---------------- host ----------------
extern "C" void kernel_launch(void* const* d_in, const int* in_sizes, int n_in,
                              void* d_out, int out_size)
{
    // Size-based identification with positional fallback.
    const float* z = nullptr; const float* ew = nullptr; const void* ei = nullptr;
    const float* mats[3] = {nullptr, nullptr, nullptr}; int nmat = 0;
    const float* vecs[2] = {nullptr, nullptr};          int nvec = 0;
    for (int i = 0; i < n_in; i++) {
        int sz = in_sizes[i];
        if      (sz == NN * HH)      z  = (const float*)d_in[i];
        else if (sz == EE)           ew = (const float*)d_in[i];
        else if (sz == 2 * EE)       ei = d_in[i];
        else if (sz == 3 * HH * HH) { if (nmat < 3) mats[nmat++] = (const float*)d_in[i]; }
        else if (sz == 3 * HH)      { if (nvec < 2) vecs[nvec++] = (const float*)d_in[i]; }
    }
    // positional fallback (metadata order: z, edge_weight, weight, w_ih, w_hh, b_ih, b_hh, edge_index)
    if (!z  && n_in > 0) z  = (const float*)d_in[0];
    if (!ew && n_in > 1) ew = (const float*)d_in[1];
    if (nmat < 3) { mats[0] = (const float*)d_in[2]; mats[1] = (const float*)d_in[3]; mats[2] = (const float*)d_in[4]; }
    if (nvec < 2) { vecs[0] = (const float*)d_in[5]; vecs[1] = (const float*)d_in[6]; }
    if (!ei && n_in > 7) ei = d_in[7];

    const float* weight = mats[0];
    const float* w_ih   = mats[1];
    const float* w_hh   = mats[2];
    const float* b_ih   = vecs[0];
    const float* b_hh   = vecs[1];
    float*       out    = (float*)d_out;

    float *pm, *pagg, *pgi, *pgh, *px, *pwih, *pwhh;
    cudaGetSymbolAddress((void**)&pm,   g_m);
    cudaGetSymbolAddress((void**)&pagg, g_agg);
    cudaGetSymbolAddress((void**)&pgi,  g_gi);
    cudaGetSymbolAddress((void**)&pgh,  g_gh);
    cudaGetSymbolAddress((void**)&px,   g_x);
    cudaGetSymbolAddress((void**)&pwih, g_wt_ih);
    cudaGetSymbolAddress((void**)&pwhh, g_wt_hh);

    const int GMX = (NN + BM - 1) / BM;               // 1563
    const int n4  = NN * (HH / 4);
    const int zgrid = (n4 + 255) / 256;
    const long long ethreads = (long long)EE * 32;
    const int egrid = (int)((ethreads + 255) / 256);  // 200000

    detect_idx_kernel<<<1, 256>>>((const int*)ei);
    transpose_w_kernel<<<(H3 * HH + 255) / 256, 256>>>(w_ih, pwih);
    transpose_w_kernel<<<(H3 * HH + 255) / 256, 256>>>(w_hh, pwhh);

    const float* x = z;
    for (int l = 0; l < LL; l++) {
        gemm_bias_kernel<<<dim3(GMX, 1), 256>>>(x, weight + (size_t)l * HH * HH,
                                                nullptr, pm, NN, HH);
        zero_kernel<<<zgrid, 256>>>((float4*)pagg, n4);
        edge_scatter_kernel<<<egrid, 256>>>(pm, ew, ei, pagg);
        gemm_bias_kernel<<<dim3(GMX, 3), 256>>>(pagg, pwih, b_ih, pgi, NN, H3);
        gemm_bias_kernel<<<dim3(GMX, 3), 256>>>(x,    pwhh, b_hh, pgh, NN, H3);
        float* xout = (l == LL - 1) ? out : px;
        gru_elem_kernel<<<zgrid, 256>>>(pgi, pgh, x, xout, n4);
        x = px;
    }
}

// round 7
// speedup vs baseline: 1.0437x; 1.0437x over previous
#include <cuda_runtime.h>
#include <cstdint>

#define NN 100000
#define EE 1600000
#define HH 128
#define H3 384
#define LL 3

// ---------------- scratch (static device globals; no allocation) ----------------
__device__ __align__(256) float g_m[(size_t)NN * HH];     // m = x @ W[l]
__device__ __align__(256) float g_agg[(size_t)NN * HH];   // scatter-add target
__device__ __align__(256) float g_gi[(size_t)NN * H3];    // agg @ w_ih^T + b_ih
__device__ __align__(256) float g_gh[(size_t)NN * H3];    // x   @ w_hh^T + b_hh
__device__ __align__(256) float g_x[(size_t)NN * HH];     // hidden state ping buffer
__device__ __align__(256) float g_wt_ih[(size_t)HH * H3]; // w_ih transposed -> [128][384]
__device__ __align__(256) float g_wt_hh[(size_t)HH * H3]; // w_hh transposed -> [128][384]
__device__ int g_idx64;                                    // 1 if edge_index buffer is int64

// ---------------- detect edge_index dtype ----------------
// int64 positive values < 2^31 have zero high words at odd 32-bit positions.
// int32 data has real indices there (all-zero over 2048 samples ~ impossible).
__global__ void detect_idx_kernel(const int* __restrict__ ei32) {
    int bad = 0;
    for (int i = threadIdx.x; i < 4096; i += blockDim.x) {
        if ((i & 1) && ei32[i] != 0) bad = 1;
    }
    bad = __syncthreads_or(bad);
    if (threadIdx.x == 0) g_idx64 = bad ? 0 : 1;
}

// ---------------- transpose [384][128] -> [128][384] ----------------
__global__ void transpose_w_kernel(const float* __restrict__ w, float* __restrict__ wt) {
    int i = blockIdx.x * blockDim.x + threadIdx.x;
    if (i < H3 * HH) {
        int j = i / HH;   // 0..383
        int k = i % HH;   // 0..127
        wt[k * H3 + j] = w[i];
    }
}

// ---------------- zero buffer (float4) ----------------
__global__ void zero_kernel(float4* __restrict__ p, int n4) {
    int i = blockIdx.x * blockDim.x + threadIdx.x;
    if (i < n4) p[i] = make_float4(0.f, 0.f, 0.f, 0.f);
}

// ---------------- tiled fp32 GEMM: C[nrows x 128k] = A[nrows x 128] @ B[128 x ncols] (+bias) ----
#define BM 64
#define KC 32
__global__ __launch_bounds__(256) void gemm_bias_kernel(
    const float* __restrict__ A, const float* __restrict__ B,
    const float* __restrict__ bias, float* __restrict__ C,
    int nrows, int ncols)
{
    __shared__ __align__(16) float Ast[KC][BM + 4];
    __shared__ __align__(16) float Bs[KC][128];

    const int tid = threadIdx.x;          // 256 threads
    const int tx  = tid & 15;             // cols tx*8 .. tx*8+7
    const int ty  = tid >> 4;             // rows ty*4 .. ty*4+3
    const int row0 = blockIdx.x * BM;
    const int col0 = blockIdx.y * 128;

    float acc[4][8];
#pragma unroll
    for (int i = 0; i < 4; i++)
#pragma unroll
        for (int j = 0; j < 8; j++) acc[i][j] = 0.f;

    const int ka = tid & 31;
    const int ra = tid >> 5;

    for (int kc = 0; kc < HH; kc += KC) {
#pragma unroll
        for (int i = 0; i < 8; i++) {
            int r = ra + i * 8;
            int grow = row0 + r;
            float v = (grow < nrows) ? A[(size_t)grow * HH + kc + ka] : 0.f;
            Ast[ka][r] = v;
        }
#pragma unroll
        for (int idx = tid; idx < KC * 128; idx += 256) {
            int kb = idx >> 7;
            int cb = idx & 127;
            Bs[kb][cb] = B[(size_t)(kc + kb) * ncols + col0 + cb];
        }
        __syncthreads();

#pragma unroll 8
        for (int k = 0; k < KC; k++) {
            float4 a  = *(const float4*)&Ast[k][ty * 4];
            float4 b0 = *(const float4*)&Bs[k][tx * 8];
            float4 b1 = *(const float4*)&Bs[k][tx * 8 + 4];
            float av[4] = {a.x, a.y, a.z, a.w};
            float bv[8] = {b0.x, b0.y, b0.z, b0.w, b1.x, b1.y, b1.z, b1.w};
#pragma unroll
            for (int i = 0; i < 4; i++)
#pragma unroll
                for (int j = 0; j < 8; j++) acc[i][j] += av[i] * bv[j];
        }
        __syncthreads();
    }

    float bvals[8];
#pragma unroll
    for (int j = 0; j < 8; j++) bvals[j] = bias ? bias[col0 + tx * 8 + j] : 0.f;

#pragma unroll
    for (int i = 0; i < 4; i++) {
        int grow = row0 + ty * 4 + i;
        if (grow < nrows) {
            float4 o0 = make_float4(acc[i][0] + bvals[0], acc[i][1] + bvals[1],
                                    acc[i][2] + bvals[2], acc[i][3] + bvals[3]);
            float4 o1 = make_float4(acc[i][4] + bvals[4], acc[i][5] + bvals[5],
                                    acc[i][6] + bvals[6], acc[i][7] + bvals[7]);
            float* crow = &C[(size_t)grow * ncols + col0 + tx * 8];
            *(float4*)(crow)     = o0;
            *(float4*)(crow + 4) = o1;
        }
    }
}

// ---------------- edge gather * weight -> vector red scatter-add ----------------
// one warp per edge; each lane handles one float4 (32 lanes * 4 = 128 features)
__global__ __launch_bounds__(256) void edge_scatter_kernel(
    const float* __restrict__ m, const float* __restrict__ ew,
    const void* __restrict__ ei, float* __restrict__ agg)
{
    long long gid = (long long)blockIdx.x * blockDim.x + threadIdx.x;
    int edge = (int)(gid >> 5);
    int lane = (int)(gid & 31);
    if (edge >= EE) return;

    int s, d;
    if (g_idx64) {
        const long long* e64 = (const long long*)ei;
        s = (int)e64[edge];
        d = (int)e64[EE + edge];
    } else {
        const int* e32 = (const int*)ei;
        s = e32[edge];
        d = e32[EE + edge];
    }
    // safety clamp: a bad index becomes a wrong answer (diagnosable), not an IMA
    if ((unsigned)s >= NN || (unsigned)d >= NN) return;

    float w = ew[edge];
    float4 v = *(const float4*)(m + (size_t)s * HH + lane * 4);
    v.x *= w; v.y *= w; v.z *= w; v.w *= w;

    float* dstp = agg + (size_t)d * HH + lane * 4;
    asm volatile("red.global.add.v4.f32 [%0], {%1, %2, %3, %4};"
                 :: "l"(dstp), "f"(v.x), "f"(v.y), "f"(v.z), "f"(v.w)
                 : "memory");
}

// ---------------- GRU elementwise ----------------
__global__ __launch_bounds__(256) void gru_elem_kernel(
    const float* __restrict__ gi, const float* __restrict__ gh,
    const float* __restrict__ x, float* __restrict__ xout, int n4)
{
    int idx = blockIdx.x * blockDim.x + threadIdx.x;
    if (idx >= n4) return;
    int node = idx >> 5;       // 32 float4 per node (H=128)
    int c4   = idx & 31;

    const float4* gi4 = (const float4*)gi;  // node stride 96 float4
    const float4* gh4 = (const float4*)gh;
    size_t base = (size_t)node * 96 + c4;

    float4 ir = gi4[base];
    float4 iz = gi4[base + 32];
    float4 in_ = gi4[base + 64];
    float4 hr = gh4[base];
    float4 hz = gh4[base + 32];
    float4 hn = gh4[base + 64];
    float4 xv = ((const float4*)x)[idx];

    float4 o;
    {
        float r  = 1.f / (1.f + __expf(-(ir.x + hr.x)));
        float zg = 1.f / (1.f + __expf(-(iz.x + hz.x)));
        float nn = tanhf(in_.x + r * hn.x);
        o.x = (1.f - zg) * nn + zg * xv.x;
    }
    {
        float r  = 1.f / (1.f + __expf(-(ir.y + hr.y)));
        float zg = 1.f / (1.f + __expf(-(iz.y + hz.y)));
        float nn = tanhf(in_.y + r * hn.y);
        o.y = (1.f - zg) * nn + zg * xv.y;
    }
    {
        float r  = 1.f / (1.f + __expf(-(ir.z + hr.z)));
        float zg = 1.f / (1.f + __expf(-(iz.z + hz.z)));
        float nn = tanhf(in_.z + r * hn.z);
        o.z = (1.f - zg) * nn + zg * xv.z;
    }
    {
        float r  = 1.f / (1.f + __expf(-(ir.w + hr.w)));
        float zg = 1.f / (1.f + __expf(-(iz.w + hz.w)));
        float nn = tanhf(in_.w + r * hn.w);
        o.w = (1.f - zg) * nn + zg * xv.w;
    }
    ((float4*)xout)[idx] = o;
}

// ---------------- host ----------------
extern "C" void kernel_launch(void* const* d_in, const int* in_sizes, int n_in,
                              void* d_out, int out_size)
{
    // Size-based identification with positional fallback.
    const float* z = nullptr; const float* ew = nullptr; const void* ei = nullptr;
    const float* mats[3] = {nullptr, nullptr, nullptr}; int nmat = 0;
    const float* vecs[2] = {nullptr, nullptr};          int nvec = 0;
    for (int i = 0; i < n_in; i++) {
        int sz = in_sizes[i];
        if      (sz == NN * HH)      z  = (const float*)d_in[i];
        else if (sz == EE)           ew = (const float*)d_in[i];
        else if (sz == 2 * EE)       ei = d_in[i];
        else if (sz == 3 * HH * HH) { if (nmat < 3) mats[nmat++] = (const float*)d_in[i]; }
        else if (sz == 3 * HH)      { if (nvec < 2) vecs[nvec++] = (const float*)d_in[i]; }
    }
    // positional fallback (metadata order: z, edge_weight, weight, w_ih, w_hh, b_ih, b_hh, edge_index)
    if (!z  && n_in > 0) z  = (const float*)d_in[0];
    if (!ew && n_in > 1) ew = (const float*)d_in[1];
    if (nmat < 3) { mats[0] = (const float*)d_in[2]; mats[1] = (const float*)d_in[3]; mats[2] = (const float*)d_in[4]; }
    if (nvec < 2) { vecs[0] = (const float*)d_in[5]; vecs[1] = (const float*)d_in[6]; }
    if (!ei && n_in > 7) ei = d_in[7];

    const float* weight = mats[0];
    const float* w_ih   = mats[1];
    const float* w_hh   = mats[2];
    const float* b_ih   = vecs[0];
    const float* b_hh   = vecs[1];
    float*       out    = (float*)d_out;

    float *pm, *pagg, *pgi, *pgh, *px, *pwih, *pwhh;
    cudaGetSymbolAddress((void**)&pm,   g_m);
    cudaGetSymbolAddress((void**)&pagg, g_agg);
    cudaGetSymbolAddress((void**)&pgi,  g_gi);
    cudaGetSymbolAddress((void**)&pgh,  g_gh);
    cudaGetSymbolAddress((void**)&px,   g_x);
    cudaGetSymbolAddress((void**)&pwih, g_wt_ih);
    cudaGetSymbolAddress((void**)&pwhh, g_wt_hh);

    const int GMX = (NN + BM - 1) / BM;               // 1563
    const int n4  = NN * (HH / 4);
    const int zgrid = (n4 + 255) / 256;
    const long long ethreads = (long long)EE * 32;
    const int egrid = (int)((ethreads + 255) / 256);  // 200000

    detect_idx_kernel<<<1, 256>>>((const int*)ei);
    transpose_w_kernel<<<(H3 * HH + 255) / 256, 256>>>(w_ih, pwih);
    transpose_w_kernel<<<(H3 * HH + 255) / 256, 256>>>(w_hh, pwhh);

    const float* x = z;
    for (int l = 0; l < LL; l++) {
        gemm_bias_kernel<<<dim3(GMX, 1), 256>>>(x, weight + (size_t)l * HH * HH,
                                                nullptr, pm, NN, HH);
        zero_kernel<<<zgrid, 256>>>((float4*)pagg, n4);
        edge_scatter_kernel<<<egrid, 256>>>(pm, ew, ei, pagg);
        gemm_bias_kernel<<<dim3(GMX, 3), 256>>>(pagg, pwih, b_ih, pgi, NN, H3);
        gemm_bias_kernel<<<dim3(GMX, 3), 256>>>(x,    pwhh, b_hh, pgh, NN, H3);
        float* xout = (l == LL - 1) ? out : px;
        gru_elem_kernel<<<zgrid, 256>>>(pgi, pgh, x, xout, n4);
        x = px;
    }
}